// round 8
// baseline (speedup 1.0000x reference)
#include <cuda_runtime.h>
#include <math.h>

#define BB 64
#define SS 1024
#define DD 128
#define HH 20
#define G4 80

// ---------------- scratch (no allocations allowed) ----------------
__device__ float g_G [BB*SS*G4];   // precomputed x@W_ih^T + (b_ih+b_hh)
__device__ float g_pw[BB*SS*HH];   // LSTM hidden states
__device__ float g_mu[BB*SS];      // per (b,j) gaussian center
__device__ float g_mnk[BB*SS];     // per (b,j): -log2(e)/(2*sigma^2)

// ---------------- small helpers ----------------
__device__ __forceinline__ unsigned long long pk2(float a, float b){
    unsigned long long r; asm("mov.b64 %0, {%1,%2};" : "=l"(r) : "f"(a), "f"(b)); return r;
}
__device__ __forceinline__ float2 upk2(unsigned long long a){
    float2 f; asm("mov.b64 {%0,%1}, %2;" : "=f"(f.x), "=f"(f.y) : "l"(a)); return f;
}
__device__ __forceinline__ unsigned long long ffma2v(unsigned long long a, unsigned long long b, unsigned long long c){
    unsigned long long d; asm("fma.rn.f32x2 %0, %1, %2, %3;" : "=l"(d) : "l"(a), "l"(b), "l"(c)); return d;
}
__device__ __forceinline__ unsigned long long add2v(unsigned long long a, unsigned long long b){
    unsigned long long d; asm("add.rn.f32x2 %0, %1, %2;" : "=l"(d) : "l"(a), "l"(b)); return d;
}
__device__ __forceinline__ float ex2f(float x){
    float r; asm("ex2.approx.ftz.f32 %0, %1;" : "=f"(r) : "f"(x)); return r;
}
// hardware tanh (MUFU.TANH, lat~16) — used in the serial LSTM recurrence
__device__ __forceinline__ float tanha(float x){
    float r; asm("tanh.approx.f32 %0, %1;" : "=f"(r) : "f"(x)); return r;
}
__device__ __forceinline__ float sigm_fast(float x){
    return fmaf(0.5f, tanha(0.5f * x), 0.5f);
}
// numerically safe sigmoid (exp-based, ~2ulp) — used in parallel k3 only
__device__ __forceinline__ float sigm(float x){
    float ax = fabsf(x);
    float e  = __expf(-ax);
    float r  = __fdividef(1.f, 1.f + e);
    return (x >= 0.f) ? r : e * r;
}

// =================================================================
// Kernel 1: G[b,s,o] = sum_d x[b,s,d]*W_ih[o,d]  + (b_ih[o]+b_hh[o])
// GEMM M=65536, N=80, K=128. Block: 64 rows, 256 threads, k split in 2 halves.
// =================================================================
__global__ __launch_bounds__(256) void k1_gates(
    const float* __restrict__ x, const float* __restrict__ Wih,
    const float* __restrict__ bih, const float* __restrict__ bhh)
{
    __shared__ float4 xs[64][17];   // 64 rows x 16 f4 (half of K), pad 17
    __shared__ float4 ws[80][17];   // 80 outs x 16 f4
    __shared__ float  bs[80];

    const int tid  = threadIdx.x;
    const int row0 = blockIdx.x * 64;
    const int og   = tid & 7;      // 8 output groups
    const int r2   = tid >> 3;     // 32 row-pairs
    const int r    = r2 * 2;

    if (tid < 80) bs[tid] = bih[tid] + bhh[tid];

    float acc0[10], acc1[10];
#pragma unroll
    for (int u = 0; u < 10; ++u){ acc0[u] = 0.f; acc1[u] = 0.f; }

    const float4* x4 = (const float4*)x;
    const float4* W4 = (const float4*)Wih;

    for (int hlf = 0; hlf < 2; ++hlf){
        __syncthreads();
        for (int i = tid; i < 64*16; i += 256){
            int rr = i >> 4, cc = i & 15;
            xs[rr][cc] = x4[(size_t)(row0 + rr) * 32 + hlf*16 + cc];
        }
        for (int i = tid; i < 80*16; i += 256){
            int oo = i >> 4, cc = i & 15;
            ws[oo][cc] = W4[(size_t)oo * 32 + hlf*16 + cc];
        }
        __syncthreads();
#pragma unroll 4
        for (int k4 = 0; k4 < 16; ++k4){
            float4 xa = xs[r][k4];
            float4 xb = xs[r+1][k4];
#pragma unroll
            for (int u = 0; u < 10; ++u){
                float4 wv = ws[og + 8*u][k4];
                acc0[u] = fmaf(xa.x, wv.x, acc0[u]);
                acc0[u] = fmaf(xa.y, wv.y, acc0[u]);
                acc0[u] = fmaf(xa.z, wv.z, acc0[u]);
                acc0[u] = fmaf(xa.w, wv.w, acc0[u]);
                acc1[u] = fmaf(xb.x, wv.x, acc1[u]);
                acc1[u] = fmaf(xb.y, wv.y, acc1[u]);
                acc1[u] = fmaf(xb.z, wv.z, acc1[u]);
                acc1[u] = fmaf(xb.w, wv.w, acc1[u]);
            }
        }
    }
    __syncthreads();
#pragma unroll
    for (int u = 0; u < 10; ++u){
        int o = og + 8*u;
        g_G[(size_t)(row0 + r    ) * G4 + o] = acc0[u] + bs[o];
        g_G[(size_t)(row0 + r + 1) * G4 + o] = acc1[u] + bs[o];
    }
}

// =================================================================
// Kernel 2: sequential LSTM. 1 warp per batch element.
// Two independent 10-deep f32x2 FMA chains per gate pair; MUFU.TANH
// for all activations.
// =================================================================
__global__ __launch_bounds__(32) void k2_lstm(const float* __restrict__ Whh)
{
    const int b  = blockIdx.x;
    const int l  = threadIdx.x;
    const int le = (l < HH) ? l : 0;

    unsigned long long wif[HH], wgo[HH];
#pragma unroll
    for (int k = 0; k < HH; ++k){
        wif[k] = pk2(Whh[(     le)*HH + k], Whh[(HH  + le)*HH + k]);
        wgo[k] = pk2(Whh[(2*HH+le)*HH + k], Whh[(3*HH+ le)*HH + k]);
    }

    float h = 0.f, c = 0.f;
    const float* Gp = g_G + (size_t)b * SS * G4;

    float a0 = Gp[le], a1 = Gp[HH+le], a2 = Gp[2*HH+le], a3 = Gp[3*HH+le];
    float b0 = Gp[G4+le], b1 = Gp[G4+HH+le], b2 = Gp[G4+2*HH+le], b3 = Gp[G4+3*HH+le];

    for (int s = 0; s < SS; ++s){
        float gi = a0, gf = a1, gg = a2, go = a3;
        a0 = b0; a1 = b1; a2 = b2; a3 = b3;
        if (s + 2 < SS){
            const float* p = Gp + (size_t)(s + 2) * G4;
            b0 = p[le]; b1 = p[HH+le]; b2 = p[2*HH+le]; b3 = p[3*HH+le];
        }
        unsigned long long aif0 = pk2(gi, gf), aif1 = 0ull;
        unsigned long long ago0 = pk2(gg, go), ago1 = 0ull;
#pragma unroll
        for (int k = 0; k < HH; k += 2){
            float hk0 = __shfl_sync(0xffffffffu, h, k);
            float hk1 = __shfl_sync(0xffffffffu, h, k + 1);
            unsigned long long h20 = pk2(hk0, hk0);
            unsigned long long h21 = pk2(hk1, hk1);
            aif0 = ffma2v(h20, wif[k],     aif0);
            aif1 = ffma2v(h21, wif[k + 1], aif1);
            ago0 = ffma2v(h20, wgo[k],     ago0);
            ago1 = ffma2v(h21, wgo[k + 1], ago1);
        }
        float2 vif = upk2(add2v(aif0, aif1));
        float2 vgo = upk2(add2v(ago0, ago1));
        float si = sigm_fast(vif.x);
        float sf = sigm_fast(vif.y);
        float tg = tanha(vgo.x);
        float so = sigm_fast(vgo.y);
        c = fmaf(sf, c, si * tg);
        h = so * tanha(c);
        if (l < HH) g_pw[((size_t)b * SS + s) * HH + l] = h;
    }
}

// =================================================================
// Kernel 3: mu_w / sigma projection + sequential affine scan for mu.
// =================================================================
__global__ __launch_bounds__(256) void k3_muscan(
    const float* __restrict__ Wmu, const float* __restrict__ bmu,
    const float* __restrict__ Wsig, const float* __restrict__ bsig)
{
    __shared__ float a_s[SS];
    __shared__ float c_s[SS];
    __shared__ float wm[3][HH];
    __shared__ float wsg[HH];
    __shared__ float bm[3];
    __shared__ float bsg;

    const int b   = blockIdx.x;
    const int tid = threadIdx.x;
    if (tid < 3*HH) wm[tid/HH][tid%HH] = Wmu[tid];
    if (tid < HH)   wsg[tid] = Wsig[tid];
    if (tid == 0){ bm[0]=bmu[0]; bm[1]=bmu[1]; bm[2]=bmu[2]; bsg = bsig[0]; }
    __syncthreads();

    for (int j = tid; j < SS; j += 256){
        const float* p = g_pw + ((size_t)b * SS + j) * HH;
        float d0 = bm[0], d1 = bm[1], d2 = bm[2], dsg = bsg;
#pragma unroll
        for (int k = 0; k < HH; ++k){
            float pv = p[k];
            d0  = fmaf(pv, wm[0][k], d0);
            d1  = fmaf(pv, wm[1][k], d1);
            d2  = fmaf(pv, wm[2][k], d2);
            dsg = fmaf(pv, wsg[k],  dsg);
        }
        float m0 = fmaxf(d0, 0.f);
        float m1 = fmaxf(d1, 0.f);
        float m2 = fmaxf(d2, 0.f);
        float sg = sigm(dsg);
        a_s[j] = m0;
        c_s[j] = m1 * (1.f/(float)SS) + m2 * ((float)(j+1) * (1.f/(float)SS));
        g_mnk[(size_t)b*SS + j] = -1.44269504088896f * __fdividef(0.5f, sg * sg);
    }
    __syncthreads();
    if (tid == 0){
        float mu = 0.f;
        float* mo = g_mu + (size_t)b * SS;
#pragma unroll 4
        for (int j = 0; j < SS; ++j){
            mu = fmaf(a_s[j], mu, c_s[j]);
            mo[j] = mu;
        }
    }
}

// =================================================================
// Kernel 4 v3: causal gaussian attention, occupancy-oriented.
// Block = (b, 64-j tile), 256 threads, 3 blocks/SM (launch_bounds).
// Per thread: 4j x 8d register tile. wsm holds {w,w} duplicated pairs.
// Inner t-iter: 16 FFMA2 + 2 LDS.128(w,broadcast) + 2 LDS.128(x).
// =================================================================
__global__ __launch_bounds__(256, 3) void k4_attn(
    const float* __restrict__ x, float* __restrict__ out)
{
    __shared__ float2 wsm[32][64];    // 16 KB: {w,w} per (t, j)
    __shared__ float4 xsm[32][32];    // 16 KB: x[t][d/4]  (total 32 KB)

    const int jt = (int)gridDim.x - 1 - (int)blockIdx.x;  // heavy tiles first
    const int b  = blockIdx.y;
    const int j0 = jt * 64;
    const int tid = threadIdx.x;

    // --- gen-phase mapping: 64 j x 32 t per tile, 8 t per thread ---
    const int jj  = tid & 63;
    const int tch = tid >> 6;            // 0..3, 8 t's each
    const int jglob = j0 + jj;
    const float muv  = g_mu [(size_t)b*SS + jglob];
    const float mnkv = g_mnk[(size_t)b*SS + jglob];
    const float invj = __fdividef(1.f, (float)(jglob + 1));
    float ssq = 0.f;

    // --- fma-phase mapping: thread handles j = j0+ty*4..+3, d = tx*8..+7 ---
    const int tx = tid & 15;
    const int ty = tid >> 4;             // 0..15
    unsigned long long acc[4][4];
#pragma unroll
    for (int r = 0; r < 4; ++r)
#pragma unroll
        for (int p = 0; p < 4; ++p) acc[r][p] = 0ull;

    const int tmax = j0 + 64;
    const float4* xg = (const float4*)(x + (size_t)b * SS * DD);

    for (int t0 = 0; t0 < tmax; t0 += 32){
        __syncthreads();
        // stage x tile: 32 rows x 32 f4 = 1024 f4
#pragma unroll
        for (int v = 0; v < 4; ++v){
            int i = v * 256 + tid;
            xsm[i >> 5][i & 31] = xg[(size_t)t0 * 32 + i];
        }
        // generate w tile, duplicated {w,w}: 8 t per thread
#pragma unroll
        for (int u = 0; u < 8; ++u){
            int t = t0 + tch * 8 + u;
            float dlt = fmaf((float)t, invj, -muv);
            float wv  = ex2f(dlt * dlt * mnkv);
            wv = (t <= jglob) ? wv : 0.f;
            wsm[tch * 8 + u][jj] = make_float2(wv, wv);
            ssq = fmaf(wv, wv, ssq);
        }
        __syncthreads();
        // FMA phase: 16 FFMA2 + 2 LDS.128(w) + 2 LDS.128(x) per t
#pragma unroll 4
        for (int t = 0; t < 32; ++t){
            const ulonglong2* wrow = (const ulonglong2*)&wsm[t][0];
            const ulonglong2* xrow = (const ulonglong2*)&xsm[t][0];
            ulonglong2 wq0 = wrow[ty*2 + 0];   // j pair {ty*4, ty*4+1}
            ulonglong2 wq1 = wrow[ty*2 + 1];   // j pair {ty*4+2, ty*4+3}
            ulonglong2 xq0 = xrow[tx*2];
            ulonglong2 xq1 = xrow[tx*2 + 1];
#define ROW(J, WV) \
            acc[J][0] = ffma2v(WV, xq0.x, acc[J][0]); \
            acc[J][1] = ffma2v(WV, xq0.y, acc[J][1]); \
            acc[J][2] = ffma2v(WV, xq1.x, acc[J][2]); \
            acc[J][3] = ffma2v(WV, xq1.y, acc[J][3]);
            ROW(0, wq0.x) ROW(1, wq0.y) ROW(2, wq1.x) ROW(3, wq1.y)
#undef ROW
        }
    }

    // epilogue: normalization (overlay scratch onto xsm, now dead)
    __syncthreads();
    float* ovl = (float*)&xsm[0][0];
    ovl[tch * 64 + jj] = ssq;                 // 4 partials x 64 j
    __syncthreads();
    if (tid < 64){
        float s2 = ovl[tid] + ovl[64 + tid] + ovl[128 + tid] + ovl[192 + tid];
        ovl[256 + tid] = __fdividef(1.f, fmaxf(sqrtf(s2), 1e-12f));
    }
    __syncthreads();

    const int d0 = tx * 8;
#pragma unroll
    for (int r = 0; r < 4; ++r){
        int jl = ty * 4 + r;
        float iv = ovl[256 + jl];
        float2 p0 = upk2(acc[r][0]);
        float2 p1 = upk2(acc[r][1]);
        float2 p2 = upk2(acc[r][2]);
        float2 p3 = upk2(acc[r][3]);
        float4* o = (float4*)&out[((size_t)b * SS + j0 + jl) * DD + d0];
        o[0] = make_float4(p0.x*iv, p0.y*iv, p1.x*iv, p1.y*iv);
        o[1] = make_float4(p2.x*iv, p2.y*iv, p3.x*iv, p3.y*iv);
    }
}

// =================================================================
extern "C" void kernel_launch(void* const* d_in, const int* in_sizes, int n_in,
                              void* d_out, int out_size)
{
    const float* x    = (const float*)d_in[0];
    const float* Wih  = (const float*)d_in[1];
    const float* Whh  = (const float*)d_in[2];
    const float* bih  = (const float*)d_in[3];
    const float* bhh  = (const float*)d_in[4];
    const float* Wmu  = (const float*)d_in[5];
    const float* bmu  = (const float*)d_in[6];
    const float* Wsig = (const float*)d_in[7];
    const float* bsig = (const float*)d_in[8];
    float* out = (float*)d_out;

    k1_gates<<<(BB*SS)/64, 256>>>(x, Wih, bih, bhh);
    k2_lstm <<<BB, 32>>>(Whh);
    k3_muscan<<<BB, 256>>>(Wmu, bmu, Wsig, bsig);
    dim3 g4(SS/64, BB);
    k4_attn<<<g4, 256>>>(x, out);
}

// round 9
// speedup vs baseline: 1.1766x; 1.1766x over previous
#include <cuda_runtime.h>
#include <math.h>

#define BB 64
#define SS 1024
#define DD 128
#define HH 20
#define G4 80

// ---------------- scratch (no allocations allowed) ----------------
__device__ float g_G [BB*SS*G4];   // precomputed x@W_ih^T + (b_ih+b_hh)
__device__ float g_pw[BB*SS*HH];   // LSTM hidden states
__device__ float g_mu[BB*SS];      // per (b,j) gaussian center
__device__ float g_mnk[BB*SS];     // per (b,j): -log2(e)/(2*sigma^2)

// ---------------- small helpers ----------------
__device__ __forceinline__ unsigned long long pk2(float a, float b){
    unsigned long long r; asm("mov.b64 %0, {%1,%2};" : "=l"(r) : "f"(a), "f"(b)); return r;
}
__device__ __forceinline__ float2 upk2(unsigned long long a){
    float2 f; asm("mov.b64 {%0,%1}, %2;" : "=f"(f.x), "=f"(f.y) : "l"(a)); return f;
}
__device__ __forceinline__ unsigned long long ffma2v(unsigned long long a, unsigned long long b, unsigned long long c){
    unsigned long long d; asm("fma.rn.f32x2 %0, %1, %2, %3;" : "=l"(d) : "l"(a), "l"(b), "l"(c)); return d;
}
__device__ __forceinline__ unsigned long long add2v(unsigned long long a, unsigned long long b){
    unsigned long long d; asm("add.rn.f32x2 %0, %1, %2;" : "=l"(d) : "l"(a), "l"(b)); return d;
}
__device__ __forceinline__ float ex2f(float x){
    float r; asm("ex2.approx.ftz.f32 %0, %1;" : "=f"(r) : "f"(x)); return r;
}
// hardware tanh (MUFU.TANH) — used in the serial LSTM recurrence
__device__ __forceinline__ float tanha(float x){
    float r; asm("tanh.approx.f32 %0, %1;" : "=f"(r) : "f"(x)); return r;
}
__device__ __forceinline__ float sigm_fast(float x){
    return fmaf(0.5f, tanha(0.5f * x), 0.5f);
}
// numerically safe sigmoid (exp-based, ~2ulp) — used in parallel k3 only
__device__ __forceinline__ float sigm(float x){
    float ax = fabsf(x);
    float e  = __expf(-ax);
    float r  = __fdividef(1.f, 1.f + e);
    return (x >= 0.f) ? r : e * r;
}
// cp.async 16B global->shared
__device__ __forceinline__ void cpa16(void* smem_dst, const void* gmem_src){
    unsigned sa = (unsigned)__cvta_generic_to_shared(smem_dst);
    asm volatile("cp.async.cg.shared.global [%0], [%1], 16;" :: "r"(sa), "l"(gmem_src));
}
__device__ __forceinline__ void cpa_commit(){ asm volatile("cp.async.commit_group;"); }
__device__ __forceinline__ void cpa_wait0(){ asm volatile("cp.async.wait_group 0;"); }

// =================================================================
// Kernel 1: G[b,s,o] = sum_d x[b,s,d]*W_ih[o,d]  + (b_ih[o]+b_hh[o])
// =================================================================
__global__ __launch_bounds__(256) void k1_gates(
    const float* __restrict__ x, const float* __restrict__ Wih,
    const float* __restrict__ bih, const float* __restrict__ bhh)
{
    __shared__ float4 xs[64][17];
    __shared__ float4 ws[80][17];
    __shared__ float  bs[80];

    const int tid  = threadIdx.x;
    const int row0 = blockIdx.x * 64;
    const int og   = tid & 7;
    const int r2   = tid >> 3;
    const int r    = r2 * 2;

    if (tid < 80) bs[tid] = bih[tid] + bhh[tid];

    float acc0[10], acc1[10];
#pragma unroll
    for (int u = 0; u < 10; ++u){ acc0[u] = 0.f; acc1[u] = 0.f; }

    const float4* x4 = (const float4*)x;
    const float4* W4 = (const float4*)Wih;

    for (int hlf = 0; hlf < 2; ++hlf){
        __syncthreads();
        for (int i = tid; i < 64*16; i += 256){
            int rr = i >> 4, cc = i & 15;
            xs[rr][cc] = x4[(size_t)(row0 + rr) * 32 + hlf*16 + cc];
        }
        for (int i = tid; i < 80*16; i += 256){
            int oo = i >> 4, cc = i & 15;
            ws[oo][cc] = W4[(size_t)oo * 32 + hlf*16 + cc];
        }
        __syncthreads();
#pragma unroll 4
        for (int k4 = 0; k4 < 16; ++k4){
            float4 xa = xs[r][k4];
            float4 xb = xs[r+1][k4];
#pragma unroll
            for (int u = 0; u < 10; ++u){
                float4 wv = ws[og + 8*u][k4];
                acc0[u] = fmaf(xa.x, wv.x, acc0[u]);
                acc0[u] = fmaf(xa.y, wv.y, acc0[u]);
                acc0[u] = fmaf(xa.z, wv.z, acc0[u]);
                acc0[u] = fmaf(xa.w, wv.w, acc0[u]);
                acc1[u] = fmaf(xb.x, wv.x, acc1[u]);
                acc1[u] = fmaf(xb.y, wv.y, acc1[u]);
                acc1[u] = fmaf(xb.z, wv.z, acc1[u]);
                acc1[u] = fmaf(xb.w, wv.w, acc1[u]);
            }
        }
    }
    __syncthreads();
#pragma unroll
    for (int u = 0; u < 10; ++u){
        int o = og + 8*u;
        g_G[(size_t)(row0 + r    ) * G4 + o] = acc0[u] + bs[o];
        g_G[(size_t)(row0 + r + 1) * G4 + o] = acc1[u] + bs[o];
    }
}

// =================================================================
// Kernel 2: sequential LSTM. 1 warp per batch element.
// =================================================================
__global__ __launch_bounds__(32) void k2_lstm(const float* __restrict__ Whh)
{
    const int b  = blockIdx.x;
    const int l  = threadIdx.x;
    const int le = (l < HH) ? l : 0;

    unsigned long long wif[HH], wgo[HH];
#pragma unroll
    for (int k = 0; k < HH; ++k){
        wif[k] = pk2(Whh[(     le)*HH + k], Whh[(HH  + le)*HH + k]);
        wgo[k] = pk2(Whh[(2*HH+le)*HH + k], Whh[(3*HH+ le)*HH + k]);
    }

    float h = 0.f, c = 0.f;
    const float* Gp = g_G + (size_t)b * SS * G4;

    float a0 = Gp[le], a1 = Gp[HH+le], a2 = Gp[2*HH+le], a3 = Gp[3*HH+le];
    float b0 = Gp[G4+le], b1 = Gp[G4+HH+le], b2 = Gp[G4+2*HH+le], b3 = Gp[G4+3*HH+le];

    for (int s = 0; s < SS; ++s){
        float gi = a0, gf = a1, gg = a2, go = a3;
        a0 = b0; a1 = b1; a2 = b2; a3 = b3;
        if (s + 2 < SS){
            const float* p = Gp + (size_t)(s + 2) * G4;
            b0 = p[le]; b1 = p[HH+le]; b2 = p[2*HH+le]; b3 = p[3*HH+le];
        }
        unsigned long long aif0 = pk2(gi, gf), aif1 = 0ull;
        unsigned long long ago0 = pk2(gg, go), ago1 = 0ull;
#pragma unroll
        for (int k = 0; k < HH; k += 2){
            float hk0 = __shfl_sync(0xffffffffu, h, k);
            float hk1 = __shfl_sync(0xffffffffu, h, k + 1);
            unsigned long long h20 = pk2(hk0, hk0);
            unsigned long long h21 = pk2(hk1, hk1);
            aif0 = ffma2v(h20, wif[k],     aif0);
            aif1 = ffma2v(h21, wif[k + 1], aif1);
            ago0 = ffma2v(h20, wgo[k],     ago0);
            ago1 = ffma2v(h21, wgo[k + 1], ago1);
        }
        float2 vif = upk2(add2v(aif0, aif1));
        float2 vgo = upk2(add2v(ago0, ago1));
        float si = sigm_fast(vif.x);
        float sf = sigm_fast(vif.y);
        float tg = tanha(vgo.x);
        float so = sigm_fast(vgo.y);
        c = fmaf(sf, c, si * tg);
        h = so * tanha(c);
        if (l < HH) g_pw[((size_t)b * SS + s) * HH + l] = h;
    }
}

// =================================================================
// Kernel 3: mu_w / sigma projection + sequential affine scan for mu.
// =================================================================
__global__ __launch_bounds__(256) void k3_muscan(
    const float* __restrict__ Wmu, const float* __restrict__ bmu,
    const float* __restrict__ Wsig, const float* __restrict__ bsig)
{
    __shared__ float a_s[SS];
    __shared__ float c_s[SS];
    __shared__ float wm[3][HH];
    __shared__ float wsg[HH];
    __shared__ float bm[3];
    __shared__ float bsg;

    const int b   = blockIdx.x;
    const int tid = threadIdx.x;
    if (tid < 3*HH) wm[tid/HH][tid%HH] = Wmu[tid];
    if (tid < HH)   wsg[tid] = Wsig[tid];
    if (tid == 0){ bm[0]=bmu[0]; bm[1]=bmu[1]; bm[2]=bmu[2]; bsg = bsig[0]; }
    __syncthreads();

    for (int j = tid; j < SS; j += 256){
        const float* p = g_pw + ((size_t)b * SS + j) * HH;
        float d0 = bm[0], d1 = bm[1], d2 = bm[2], dsg = bsg;
#pragma unroll
        for (int k = 0; k < HH; ++k){
            float pv = p[k];
            d0  = fmaf(pv, wm[0][k], d0);
            d1  = fmaf(pv, wm[1][k], d1);
            d2  = fmaf(pv, wm[2][k], d2);
            dsg = fmaf(pv, wsg[k],  dsg);
        }
        float m0 = fmaxf(d0, 0.f);
        float m1 = fmaxf(d1, 0.f);
        float m2 = fmaxf(d2, 0.f);
        float sg = sigm(dsg);
        a_s[j] = m0;
        c_s[j] = m1 * (1.f/(float)SS) + m2 * ((float)(j+1) * (1.f/(float)SS));
        g_mnk[(size_t)b*SS + j] = -1.44269504088896f * __fdividef(0.5f, sg * sg);
    }
    __syncthreads();
    if (tid == 0){
        float mu = 0.f;
        float* mo = g_mu + (size_t)b * SS;
#pragma unroll 4
        for (int j = 0; j < SS; ++j){
            mu = fmaf(a_s[j], mu, c_s[j]);
            mo[j] = mu;
        }
    }
}

// =================================================================
// Kernel 4 v4: R3 tiling (best measured: w plain in smem, x MOV-dup,
// 8j x 8d per thread) + double-buffered 16-t pipeline:
//  - w for tile i+1 computed & STS'd before FMA of tile i (no LDG dep)
//  - x for tile i+1 fetched via cp.async (overlaps FMA fully)
//  - ONE __syncthreads per tile instead of two
// =================================================================
__global__ __launch_bounds__(256) void k4_attn(
    const float* __restrict__ x, float* __restrict__ out)
{
    __shared__ float  wsm[2][16][128];   // 16 KB: w[t][j], plain
    __shared__ float4 xsm[2][16][32];    // 16 KB: x[t][d/4]
    __shared__ float  ssqs[2][128];
    __shared__ float  innorm[128];

    const int jt = (int)gridDim.x - 1 - (int)blockIdx.x;  // heavy tiles first
    const int b  = blockIdx.y;
    const int j0 = jt * 128;
    const int tid = threadIdx.x;

    // --- gen mapping: 128 j x 16 t per tile; 8 t per thread ---
    const int jj  = tid & 127;
    const int tch = tid >> 7;            // 0..1, 8 t's each
    const int jglob = j0 + jj;
    const float muv  = g_mu [(size_t)b*SS + jglob];
    const float mnkv = g_mnk[(size_t)b*SS + jglob];
    const float invj = __fdividef(1.f, (float)(jglob + 1));
    float ssq = 0.f;

    // --- fma mapping: thread handles j-pairs p=0..3 (j = ty*8+2p,+1), d = tx*8..+7 ---
    const int tx = tid & 15;
    const int ty = tid >> 4;
    unsigned long long acc[4][8];
#pragma unroll
    for (int p = 0; p < 4; ++p)
#pragma unroll
        for (int dd = 0; dd < 8; ++dd) acc[p][dd] = 0ull;

    const int ntiles = (j0 + 128) / 16;
    const float4* xg = (const float4*)(x + (size_t)b * SS * DD);

    // ---- stage tile i into buffer buf: w gen (STS) + x cp.async ----
    #define STAGE(I, BUF) do {                                              \
        int t0_ = (I) * 16;                                                 \
        _Pragma("unroll")                                                   \
        for (int u = 0; u < 8; ++u){                                        \
            int t = t0_ + tch * 8 + u;                                      \
            float dlt = fmaf((float)t, invj, -muv);                         \
            float wv  = ex2f(dlt * dlt * mnkv);                             \
            wv = (t <= jglob) ? wv : 0.f;                                   \
            wsm[BUF][tch * 8 + u][jj] = wv;                                 \
            ssq = fmaf(wv, wv, ssq);                                        \
        }                                                                   \
        _Pragma("unroll")                                                   \
        for (int v = 0; v < 2; ++v){                                        \
            int i_ = v * 256 + tid;                                         \
            cpa16(&xsm[BUF][i_ >> 5][i_ & 31], &xg[(size_t)t0_ * 32 + i_]); \
        }                                                                   \
        cpa_commit();                                                       \
    } while(0)

    STAGE(0, 0);
    cpa_wait0();
    __syncthreads();

    for (int i = 0; i < ntiles; ++i){
        const int cur = i & 1;
        const bool more = (i + 1 < ntiles);
        if (more) STAGE(i + 1, cur ^ 1);

        // FMA phase on buffer cur: per t: 4 LDS.64(w) + 2 LDS.128(x) + 8 MOV + 32 FFMA2
#pragma unroll 2
        for (int t = 0; t < 16; ++t){
            const unsigned long long* wrow = (const unsigned long long*)&wsm[cur][t][0];
            unsigned long long wv0 = wrow[ty*4 + 0];
            unsigned long long wv1 = wrow[ty*4 + 1];
            unsigned long long wv2 = wrow[ty*4 + 2];
            unsigned long long wv3 = wrow[ty*4 + 3];
            float4 xa = xsm[cur][t][tx*2];
            float4 xb = xsm[cur][t][tx*2 + 1];
            unsigned long long xx0 = pk2(xa.x, xa.x);
            unsigned long long xx1 = pk2(xa.y, xa.y);
            unsigned long long xx2 = pk2(xa.z, xa.z);
            unsigned long long xx3 = pk2(xa.w, xa.w);
            unsigned long long xx4 = pk2(xb.x, xb.x);
            unsigned long long xx5 = pk2(xb.y, xb.y);
            unsigned long long xx6 = pk2(xb.z, xb.z);
            unsigned long long xx7 = pk2(xb.w, xb.w);
#define STEP(P, WV) \
            acc[P][0] = ffma2v(WV, xx0, acc[P][0]); \
            acc[P][1] = ffma2v(WV, xx1, acc[P][1]); \
            acc[P][2] = ffma2v(WV, xx2, acc[P][2]); \
            acc[P][3] = ffma2v(WV, xx3, acc[P][3]); \
            acc[P][4] = ffma2v(WV, xx4, acc[P][4]); \
            acc[P][5] = ffma2v(WV, xx5, acc[P][5]); \
            acc[P][6] = ffma2v(WV, xx6, acc[P][6]); \
            acc[P][7] = ffma2v(WV, xx7, acc[P][7]);
            STEP(0, wv0) STEP(1, wv1) STEP(2, wv2) STEP(3, wv3)
#undef STEP
        }
        if (more) cpa_wait0();
        __syncthreads();
    }
    #undef STAGE

    // epilogue: L2 normalization
    ssqs[tch][jj] = ssq;
    __syncthreads();
    if (tid < 128){
        float s2 = ssqs[0][tid] + ssqs[1][tid];
        innorm[tid] = __fdividef(1.f, fmaxf(sqrtf(s2), 1e-12f));
    }
    __syncthreads();

    const int d0 = tx * 8;
#pragma unroll
    for (int p = 0; p < 4; ++p){
        int jl = ty * 8 + p * 2;
        int j  = j0 + jl;
        float i0 = innorm[jl];
        float i1 = innorm[jl + 1];
        float2 q0 = upk2(acc[p][0]);
        float2 q1 = upk2(acc[p][1]);
        float2 q2 = upk2(acc[p][2]);
        float2 q3 = upk2(acc[p][3]);
        float2 q4 = upk2(acc[p][4]);
        float2 q5 = upk2(acc[p][5]);
        float2 q6 = upk2(acc[p][6]);
        float2 q7 = upk2(acc[p][7]);
        float4* o0 = (float4*)&out[((size_t)b * SS + j    ) * DD + d0];
        float4* o1 = (float4*)&out[((size_t)b * SS + j + 1) * DD + d0];
        o0[0] = make_float4(q0.x*i0, q1.x*i0, q2.x*i0, q3.x*i0);
        o0[1] = make_float4(q4.x*i0, q5.x*i0, q6.x*i0, q7.x*i0);
        o1[0] = make_float4(q0.y*i1, q1.y*i1, q2.y*i1, q3.y*i1);
        o1[1] = make_float4(q4.y*i1, q5.y*i1, q6.y*i1, q7.y*i1);
    }
}

// =================================================================
extern "C" void kernel_launch(void* const* d_in, const int* in_sizes, int n_in,
                              void* d_out, int out_size)
{
    const float* x    = (const float*)d_in[0];
    const float* Wih  = (const float*)d_in[1];
    const float* Whh  = (const float*)d_in[2];
    const float* bih  = (const float*)d_in[3];
    const float* bhh  = (const float*)d_in[4];
    const float* Wmu  = (const float*)d_in[5];
    const float* bmu  = (const float*)d_in[6];
    const float* Wsig = (const float*)d_in[7];
    const float* bsig = (const float*)d_in[8];
    float* out = (float*)d_out;

    k1_gates<<<(BB*SS)/64, 256>>>(x, Wih, bih, bhh);
    k2_lstm <<<BB, 32>>>(Whh);
    k3_muscan<<<BB, 256>>>(Wmu, bmu, Wsig, bsig);
    dim3 g4(SS/128, BB);
    k4_attn<<<g4, 256>>>(x, out);
}

// round 11
// speedup vs baseline: 1.4488x; 1.2313x over previous
#include <cuda_runtime.h>
#include <math.h>

#define BB 64
#define SS 1024
#define DD 128
#define HH 20
#define G4 80

// ---------------- scratch (no allocations allowed) ----------------
__device__ float g_G [BB*SS*G4];   // precomputed x@W_ih^T + (b_ih+b_hh)
__device__ float g_pw[BB*SS*HH];   // LSTM hidden states
__device__ float g_mu[BB*SS];      // per (b,j) gaussian center
__device__ float g_mnk[BB*SS];     // per (b,j): -log2(e)/(2*sigma^2)

// ---------------- small helpers ----------------
__device__ __forceinline__ unsigned long long pk2(float a, float b){
    unsigned long long r; asm("mov.b64 %0, {%1,%2};" : "=l"(r) : "f"(a), "f"(b)); return r;
}
__device__ __forceinline__ float2 upk2(unsigned long long a){
    float2 f; asm("mov.b64 {%0,%1}, %2;" : "=f"(f.x), "=f"(f.y) : "l"(a)); return f;
}
__device__ __forceinline__ unsigned long long ffma2v(unsigned long long a, unsigned long long b, unsigned long long c){
    unsigned long long d; asm("fma.rn.f32x2 %0, %1, %2, %3;" : "=l"(d) : "l"(a), "l"(b), "l"(c)); return d;
}
__device__ __forceinline__ unsigned long long add2v(unsigned long long a, unsigned long long b){
    unsigned long long d; asm("add.rn.f32x2 %0, %1, %2;" : "=l"(d) : "l"(a), "l"(b)); return d;
}
__device__ __forceinline__ float ex2f(float x){
    float r; asm("ex2.approx.ftz.f32 %0, %1;" : "=f"(r) : "f"(x)); return r;
}
// hardware tanh (MUFU.TANH) — used in the serial LSTM recurrence
__device__ __forceinline__ float tanha(float x){
    float r; asm("tanh.approx.f32 %0, %1;" : "=f"(r) : "f"(x)); return r;
}
__device__ __forceinline__ float sigm_fast(float x){
    return fmaf(0.5f, tanha(0.5f * x), 0.5f);
}
// numerically safe sigmoid (exp-based, ~2ulp) — used in parallel k3 only
__device__ __forceinline__ float sigm(float x){
    float ax = fabsf(x);
    float e  = __expf(-ax);
    float r  = __fdividef(1.f, 1.f + e);
    return (x >= 0.f) ? r : e * r;
}

// =================================================================
// Kernel 1: G[b,s,o] = sum_d x[b,s,d]*W_ih[o,d]  + (b_ih[o]+b_hh[o])
// (unchanged — control)
// =================================================================
__global__ __launch_bounds__(256) void k1_gates(
    const float* __restrict__ x, const float* __restrict__ Wih,
    const float* __restrict__ bih, const float* __restrict__ bhh)
{
    __shared__ float4 xs[64][17];
    __shared__ float4 ws[80][17];
    __shared__ float  bs[80];

    const int tid  = threadIdx.x;
    const int row0 = blockIdx.x * 64;
    const int og   = tid & 7;
    const int r2   = tid >> 3;
    const int r    = r2 * 2;

    if (tid < 80) bs[tid] = bih[tid] + bhh[tid];

    float acc0[10], acc1[10];
#pragma unroll
    for (int u = 0; u < 10; ++u){ acc0[u] = 0.f; acc1[u] = 0.f; }

    const float4* x4 = (const float4*)x;
    const float4* W4 = (const float4*)Wih;

    for (int hlf = 0; hlf < 2; ++hlf){
        __syncthreads();
        for (int i = tid; i < 64*16; i += 256){
            int rr = i >> 4, cc = i & 15;
            xs[rr][cc] = x4[(size_t)(row0 + rr) * 32 + hlf*16 + cc];
        }
        for (int i = tid; i < 80*16; i += 256){
            int oo = i >> 4, cc = i & 15;
            ws[oo][cc] = W4[(size_t)oo * 32 + hlf*16 + cc];
        }
        __syncthreads();
#pragma unroll 4
        for (int k4 = 0; k4 < 16; ++k4){
            float4 xa = xs[r][k4];
            float4 xb = xs[r+1][k4];
#pragma unroll
            for (int u = 0; u < 10; ++u){
                float4 wv = ws[og + 8*u][k4];
                acc0[u] = fmaf(xa.x, wv.x, acc0[u]);
                acc0[u] = fmaf(xa.y, wv.y, acc0[u]);
                acc0[u] = fmaf(xa.z, wv.z, acc0[u]);
                acc0[u] = fmaf(xa.w, wv.w, acc0[u]);
                acc1[u] = fmaf(xb.x, wv.x, acc1[u]);
                acc1[u] = fmaf(xb.y, wv.y, acc1[u]);
                acc1[u] = fmaf(xb.z, wv.z, acc1[u]);
                acc1[u] = fmaf(xb.w, wv.w, acc1[u]);
            }
        }
    }
    __syncthreads();
#pragma unroll
    for (int u = 0; u < 10; ++u){
        int o = og + 8*u;
        g_G[(size_t)(row0 + r    ) * G4 + o] = acc0[u] + bs[o];
        g_G[(size_t)(row0 + r + 1) * G4 + o] = acc1[u] + bs[o];
    }
}

// =================================================================
// Kernel 2: sequential LSTM, 1 warp per batch element.
// 4-deep register prefetch of g_G rows. FIXED vs R10: the current
// step's gate values are folded into pk2() accumulators BEFORE the
// prefetch overwrites the (aliased) registers.
// =================================================================
__global__ __launch_bounds__(32) void k2_lstm(const float* __restrict__ Whh)
{
    const int b  = blockIdx.x;
    const int l  = threadIdx.x;
    const int le = (l < HH) ? l : 0;

    unsigned long long wif[HH], wgo[HH];
#pragma unroll
    for (int k = 0; k < HH; ++k){
        wif[k] = pk2(Whh[(     le)*HH + k], Whh[(HH  + le)*HH + k]);
        wgo[k] = pk2(Whh[(2*HH+le)*HH + k], Whh[(3*HH+ le)*HH + k]);
    }

    float h = 0.f, c = 0.f;
    const float* Gp = g_G + (size_t)b * SS * G4;

    // 4 named prefetch sets (A=s, B=s+1, C=s+2, D=s+3)
    float A0 = Gp[le],        A1 = Gp[HH+le],        A2 = Gp[2*HH+le],        A3 = Gp[3*HH+le];
    float B0 = Gp[G4+le],     B1 = Gp[G4+HH+le],     B2 = Gp[G4+2*HH+le],     B3 = Gp[G4+3*HH+le];
    float C0 = Gp[2*G4+le],   C1 = Gp[2*G4+HH+le],   C2 = Gp[2*G4+2*HH+le],   C3 = Gp[2*G4+3*HH+le];
    float D0 = Gp[3*G4+le],   D1 = Gp[3*G4+HH+le],   D2 = Gp[3*G4+2*HH+le],   D3 = Gp[3*G4+3*HH+le];

    // CONSUME FIRST (gates captured into aif0/ago0), THEN prefetch into the
    // same (rotated) registers — aliasing is now safe by construction.
#define LSTM_STEP(SCUR, G0, G1, G2, G3, R0, R1, R2, R3)                        \
    {                                                                          \
        unsigned long long aif0 = pk2(G0, G1), aif1 = 0ull;                    \
        unsigned long long ago0 = pk2(G2, G3), ago1 = 0ull;                    \
        const int sn_ = (SCUR) + 4;                                            \
        if (sn_ < SS){                                                         \
            const float* p_ = Gp + (size_t)sn_ * G4;                           \
            R0 = p_[le]; R1 = p_[HH+le]; R2 = p_[2*HH+le]; R3 = p_[3*HH+le];   \
        }                                                                      \
        _Pragma("unroll")                                                      \
        for (int k = 0; k < HH; k += 2){                                       \
            float hk0 = __shfl_sync(0xffffffffu, h, k);                        \
            float hk1 = __shfl_sync(0xffffffffu, h, k + 1);                    \
            unsigned long long h20 = pk2(hk0, hk0);                            \
            unsigned long long h21 = pk2(hk1, hk1);                            \
            aif0 = ffma2v(h20, wif[k],     aif0);                              \
            aif1 = ffma2v(h21, wif[k + 1], aif1);                              \
            ago0 = ffma2v(h20, wgo[k],     ago0);                              \
            ago1 = ffma2v(h21, wgo[k + 1], ago1);                              \
        }                                                                      \
        float2 vif = upk2(add2v(aif0, aif1));                                  \
        float2 vgo = upk2(add2v(ago0, ago1));                                  \
        float si = sigm_fast(vif.x);                                           \
        float sf = sigm_fast(vif.y);                                           \
        float tg = tanha(vgo.x);                                               \
        float so = sigm_fast(vgo.y);                                           \
        c = fmaf(sf, c, si * tg);                                              \
        h = so * tanha(c);                                                     \
        if (l < HH) g_pw[((size_t)b * SS + (SCUR)) * HH + l] = h;              \
    }

    for (int s = 0; s < SS; s += 4){
        LSTM_STEP(s    , A0, A1, A2, A3, A0, A1, A2, A3);
        LSTM_STEP(s + 1, B0, B1, B2, B3, B0, B1, B2, B3);
        LSTM_STEP(s + 2, C0, C1, C2, C3, C0, C1, C2, C3);
        LSTM_STEP(s + 3, D0, D1, D2, D3, D0, D1, D2, D3);
    }
#undef LSTM_STEP
}

// =================================================================
// Kernel 3: mu_w / sigma projection + sequential affine scan for mu.
// (unchanged — control)
// =================================================================
__global__ __launch_bounds__(256) void k3_muscan(
    const float* __restrict__ Wmu, const float* __restrict__ bmu,
    const float* __restrict__ Wsig, const float* __restrict__ bsig)
{
    __shared__ float a_s[SS];
    __shared__ float c_s[SS];
    __shared__ float wm[3][HH];
    __shared__ float wsg[HH];
    __shared__ float bm[3];
    __shared__ float bsg;

    const int b   = blockIdx.x;
    const int tid = threadIdx.x;
    if (tid < 3*HH) wm[tid/HH][tid%HH] = Wmu[tid];
    if (tid < HH)   wsg[tid] = Wsig[tid];
    if (tid == 0){ bm[0]=bmu[0]; bm[1]=bmu[1]; bm[2]=bmu[2]; bsg = bsig[0]; }
    __syncthreads();

    for (int j = tid; j < SS; j += 256){
        const float* p = g_pw + ((size_t)b * SS + j) * HH;
        float d0 = bm[0], d1 = bm[1], d2 = bm[2], dsg = bsg;
#pragma unroll
        for (int k = 0; k < HH; ++k){
            float pv = p[k];
            d0  = fmaf(pv, wm[0][k], d0);
            d1  = fmaf(pv, wm[1][k], d1);
            d2  = fmaf(pv, wm[2][k], d2);
            dsg = fmaf(pv, wsg[k],  dsg);
        }
        float m0 = fmaxf(d0, 0.f);
        float m1 = fmaxf(d1, 0.f);
        float m2 = fmaxf(d2, 0.f);
        float sg = sigm(dsg);
        a_s[j] = m0;
        c_s[j] = m1 * (1.f/(float)SS) + m2 * ((float)(j+1) * (1.f/(float)SS));
        g_mnk[(size_t)b*SS + j] = -1.44269504088896f * __fdividef(0.5f, sg * sg);
    }
    __syncthreads();
    if (tid == 0){
        float mu = 0.f;
        float* mo = g_mu + (size_t)b * SS;
#pragma unroll 4
        for (int j = 0; j < SS; ++j){
            mu = fmaf(a_s[j], mu, c_s[j]);
            mo[j] = mu;
        }
    }
}

// =================================================================
// Kernel 4: causal gaussian attention — best-measured R3 variant
// (308.7 us): w plain in smem, x duplicated via register MOVs,
// 8j x 8d per thread, 32-t tiles, two syncthreads per tile.
// =================================================================
__global__ __launch_bounds__(256) void k4_attn(
    const float* __restrict__ x, float* __restrict__ out)
{
    __shared__ float  wsm[32][128];       // w[t][j]
    __shared__ float4 xsm[32][32];        // x[t][d/4]
    __shared__ float  ssqs[2][128];
    __shared__ float  innorm[128];

    const int jt = (int)gridDim.x - 1 - (int)blockIdx.x;  // heavy tiles first
    const int b  = blockIdx.y;
    const int j0 = jt * 128;
    const int tid = threadIdx.x;

    const int jj  = tid & 127;
    const int tch = tid >> 7;            // 0..1, 16 t's each
    const int jglob = j0 + jj;
    const float muv  = g_mu [(size_t)b*SS + jglob];
    const float mnkv = g_mnk[(size_t)b*SS + jglob];
    const float invj = __fdividef(1.f, (float)(jglob + 1));
    float ssq = 0.f;

    const int tx = tid & 15;
    const int ty = tid >> 4;
    unsigned long long acc[4][8];
#pragma unroll
    for (int p = 0; p < 4; ++p)
#pragma unroll
        for (int dd = 0; dd < 8; ++dd) acc[p][dd] = 0ull;

    const int tmax = j0 + 128;
    const float4* xg = (const float4*)(x + (size_t)b * SS * DD);

    for (int t0 = 0; t0 < tmax; t0 += 32){
        __syncthreads();
#pragma unroll
        for (int v = 0; v < 4; ++v){
            int i = v * 256 + tid;
            xsm[i >> 5][i & 31] = xg[(size_t)t0 * 32 + i];
        }
#pragma unroll
        for (int u = 0; u < 16; ++u){
            int t = t0 + tch * 16 + u;
            float tf  = (float)t;
            float dlt = fmaf(tf, invj, -muv);
            float wv  = ex2f(dlt * dlt * mnkv);
            wv = (t <= jglob) ? wv : 0.f;
            wsm[tch * 16 + u][jj] = wv;
            ssq = fmaf(wv, wv, ssq);
        }
        __syncthreads();
#pragma unroll 2
        for (int t = 0; t < 32; ++t){
            const double* wrow = (const double*)&wsm[t][0];
            unsigned long long wv0 = ((const unsigned long long*)wrow)[ty*4 + 0];
            unsigned long long wv1 = ((const unsigned long long*)wrow)[ty*4 + 1];
            unsigned long long wv2 = ((const unsigned long long*)wrow)[ty*4 + 2];
            unsigned long long wv3 = ((const unsigned long long*)wrow)[ty*4 + 3];
            float4 xa = xsm[t][tx*2];
            float4 xb = xsm[t][tx*2 + 1];
            unsigned long long xx0 = pk2(xa.x, xa.x);
            unsigned long long xx1 = pk2(xa.y, xa.y);
            unsigned long long xx2 = pk2(xa.z, xa.z);
            unsigned long long xx3 = pk2(xa.w, xa.w);
            unsigned long long xx4 = pk2(xb.x, xb.x);
            unsigned long long xx5 = pk2(xb.y, xb.y);
            unsigned long long xx6 = pk2(xb.z, xb.z);
            unsigned long long xx7 = pk2(xb.w, xb.w);
#define STEP(P, WV) \
            acc[P][0] = ffma2v(WV, xx0, acc[P][0]); \
            acc[P][1] = ffma2v(WV, xx1, acc[P][1]); \
            acc[P][2] = ffma2v(WV, xx2, acc[P][2]); \
            acc[P][3] = ffma2v(WV, xx3, acc[P][3]); \
            acc[P][4] = ffma2v(WV, xx4, acc[P][4]); \
            acc[P][5] = ffma2v(WV, xx5, acc[P][5]); \
            acc[P][6] = ffma2v(WV, xx6, acc[P][6]); \
            acc[P][7] = ffma2v(WV, xx7, acc[P][7]);
            STEP(0, wv0) STEP(1, wv1) STEP(2, wv2) STEP(3, wv3)
#undef STEP
        }
    }

    __syncthreads();
    ssqs[tch][jj] = ssq;
    __syncthreads();
    if (tid < 128){
        float s2 = ssqs[0][tid] + ssqs[1][tid];
        innorm[tid] = __fdividef(1.f, fmaxf(sqrtf(s2), 1e-12f));
    }
    __syncthreads();

    const int d0 = tx * 8;
#pragma unroll
    for (int p = 0; p < 4; ++p){
        int jl = ty * 8 + p * 2;
        int j  = j0 + jl;
        float i0 = innorm[jl];
        float i1 = innorm[jl + 1];
        float2 q0 = upk2(acc[p][0]);
        float2 q1 = upk2(acc[p][1]);
        float2 q2 = upk2(acc[p][2]);
        float2 q3 = upk2(acc[p][3]);
        float2 q4 = upk2(acc[p][4]);
        float2 q5 = upk2(acc[p][5]);
        float2 q6 = upk2(acc[p][6]);
        float2 q7 = upk2(acc[p][7]);
        float4* o0 = (float4*)&out[((size_t)b * SS + j    ) * DD + d0];
        float4* o1 = (float4*)&out[((size_t)b * SS + j + 1) * DD + d0];
        o0[0] = make_float4(q0.x*i0, q1.x*i0, q2.x*i0, q3.x*i0);
        o0[1] = make_float4(q4.x*i0, q5.x*i0, q6.x*i0, q7.x*i0);
        o1[0] = make_float4(q0.y*i1, q1.y*i1, q2.y*i1, q3.y*i1);
        o1[1] = make_float4(q4.y*i1, q5.y*i1, q6.y*i1, q7.y*i1);
    }
}

// =================================================================
extern "C" void kernel_launch(void* const* d_in, const int* in_sizes, int n_in,
                              void* d_out, int out_size)
{
    const float* x    = (const float*)d_in[0];
    const float* Wih  = (const float*)d_in[1];
    const float* Whh  = (const float*)d_in[2];
    const float* bih  = (const float*)d_in[3];
    const float* bhh  = (const float*)d_in[4];
    const float* Wmu  = (const float*)d_in[5];
    const float* bmu  = (const float*)d_in[6];
    const float* Wsig = (const float*)d_in[7];
    const float* bsig = (const float*)d_in[8];
    float* out = (float*)d_out;

    k1_gates<<<(BB*SS)/64, 256>>>(x, Wih, bih, bhh);
    k2_lstm <<<BB, 32>>>(Whh);
    k3_muscan<<<BB, 256>>>(Wmu, bmu, Wsig, bsig);
    dim3 g4(SS/128, BB);
    k4_attn<<<g4, 256>>>(x, out);
}

// round 12
// speedup vs baseline: 1.4696x; 1.0144x over previous
#include <cuda_runtime.h>
#include <math.h>

#define BB 64
#define SS 1024
#define DD 128
#define HH 20
#define G4 80

// ---------------- scratch (no allocations allowed) ----------------
// g_G layout is GATE-INTERLEAVED: row (b,s) holds unit-major float4s:
//   g_G[(b*SS+s)*G4 + unit*4 + gate],  gate: 0=i,1=f,2=g,3=o
__device__ float g_G [BB*SS*G4];
__device__ float g_pw[BB*SS*HH];   // LSTM hidden states
__device__ float g_mu[BB*SS];      // per (b,j) gaussian center
__device__ float g_mnk[BB*SS];     // per (b,j): -log2(e)/(2*sigma^2)

// ---------------- small helpers ----------------
__device__ __forceinline__ unsigned long long pk2(float a, float b){
    unsigned long long r; asm("mov.b64 %0, {%1,%2};" : "=l"(r) : "f"(a), "f"(b)); return r;
}
__device__ __forceinline__ float2 upk2(unsigned long long a){
    float2 f; asm("mov.b64 {%0,%1}, %2;" : "=f"(f.x), "=f"(f.y) : "l"(a)); return f;
}
__device__ __forceinline__ unsigned long long ffma2v(unsigned long long a, unsigned long long b, unsigned long long c){
    unsigned long long d; asm("fma.rn.f32x2 %0, %1, %2, %3;" : "=l"(d) : "l"(a), "l"(b), "l"(c)); return d;
}
__device__ __forceinline__ unsigned long long add2v(unsigned long long a, unsigned long long b){
    unsigned long long d; asm("add.rn.f32x2 %0, %1, %2;" : "=l"(d) : "l"(a), "l"(b)); return d;
}
__device__ __forceinline__ float ex2f(float x){
    float r; asm("ex2.approx.ftz.f32 %0, %1;" : "=f"(r) : "f"(x)); return r;
}
// hardware tanh (MUFU.TANH) — used in the serial LSTM recurrence
__device__ __forceinline__ float tanha(float x){
    float r; asm("tanh.approx.f32 %0, %1;" : "=f"(r) : "f"(x)); return r;
}
__device__ __forceinline__ float sigm_fast(float x){
    return fmaf(0.5f, tanha(0.5f * x), 0.5f);
}
// numerically safe sigmoid (exp-based, ~2ulp) — used in parallel k3 only
__device__ __forceinline__ float sigm(float x){
    float ax = fabsf(x);
    float e  = __expf(-ax);
    float r  = __fdividef(1.f, 1.f + e);
    return (x >= 0.f) ? r : e * r;
}

// =================================================================
// Kernel 1: G[b,s,:] = x[b,s,:]@W_ih^T + (b_ih+b_hh), stored
// gate-interleaved (unit*4+gate). Only the epilogue differs from the
// measured baseline.
// =================================================================
__global__ __launch_bounds__(256) void k1_gates(
    const float* __restrict__ x, const float* __restrict__ Wih,
    const float* __restrict__ bih, const float* __restrict__ bhh)
{
    __shared__ float4 xs[64][17];
    __shared__ float4 ws[80][17];
    __shared__ float  bs[80];

    const int tid  = threadIdx.x;
    const int row0 = blockIdx.x * 64;
    const int og   = tid & 7;
    const int r2   = tid >> 3;
    const int r    = r2 * 2;

    if (tid < 80) bs[tid] = bih[tid] + bhh[tid];

    float acc0[10], acc1[10];
#pragma unroll
    for (int u = 0; u < 10; ++u){ acc0[u] = 0.f; acc1[u] = 0.f; }

    const float4* x4 = (const float4*)x;
    const float4* W4 = (const float4*)Wih;

    for (int hlf = 0; hlf < 2; ++hlf){
        __syncthreads();
        for (int i = tid; i < 64*16; i += 256){
            int rr = i >> 4, cc = i & 15;
            xs[rr][cc] = x4[(size_t)(row0 + rr) * 32 + hlf*16 + cc];
        }
        for (int i = tid; i < 80*16; i += 256){
            int oo = i >> 4, cc = i & 15;
            ws[oo][cc] = W4[(size_t)oo * 32 + hlf*16 + cc];
        }
        __syncthreads();
#pragma unroll 4
        for (int k4 = 0; k4 < 16; ++k4){
            float4 xa = xs[r][k4];
            float4 xb = xs[r+1][k4];
#pragma unroll
            for (int u = 0; u < 10; ++u){
                float4 wv = ws[og + 8*u][k4];
                acc0[u] = fmaf(xa.x, wv.x, acc0[u]);
                acc0[u] = fmaf(xa.y, wv.y, acc0[u]);
                acc0[u] = fmaf(xa.z, wv.z, acc0[u]);
                acc0[u] = fmaf(xa.w, wv.w, acc0[u]);
                acc1[u] = fmaf(xb.x, wv.x, acc1[u]);
                acc1[u] = fmaf(xb.y, wv.y, acc1[u]);
                acc1[u] = fmaf(xb.z, wv.z, acc1[u]);
                acc1[u] = fmaf(xb.w, wv.w, acc1[u]);
            }
        }
    }
    __syncthreads();
#pragma unroll
    for (int u = 0; u < 10; ++u){
        int o    = og + 8*u;          // W_ih row: gate = o/20, unit = o%20
        int gate = o / HH;
        int unit = o - gate * HH;
        int off  = unit * 4 + gate;   // gate-interleaved position
        g_G[(size_t)(row0 + r    ) * G4 + off] = acc0[u] + bs[o];
        g_G[(size_t)(row0 + r + 1) * G4 + off] = acc1[u] + bs[o];
    }
}

// =================================================================
// Kernel 2: sequential LSTM, 1 warp per batch element.
// Gate-interleaved g_G -> ONE LDG.128 per step per lane (coalesced
// 320B/row). 8-deep float4 register prefetch rotation (consume first,
// then prefetch into the rotated register — R11-validated pattern).
// =================================================================
__global__ __launch_bounds__(32) void k2_lstm(const float* __restrict__ Whh)
{
    const int b  = blockIdx.x;
    const int l  = threadIdx.x;
    const int le = (l < HH) ? l : 0;

    unsigned long long wif[HH], wgo[HH];
#pragma unroll
    for (int k = 0; k < HH; ++k){
        wif[k] = pk2(Whh[(     le)*HH + k], Whh[(HH  + le)*HH + k]);
        wgo[k] = pk2(Whh[(2*HH+le)*HH + k], Whh[(3*HH+ le)*HH + k]);
    }

    float h = 0.f, c = 0.f;
    const float4* Gp4 = (const float4*)(g_G + (size_t)b * SS * G4);
    const int lane4 = le;            // float4 index within a 20-f4 row

    // 8 named prefetch sets
    float4 A = Gp4[0*20 + lane4];
    float4 B = Gp4[1*20 + lane4];
    float4 C = Gp4[2*20 + lane4];
    float4 D = Gp4[3*20 + lane4];
    float4 E = Gp4[4*20 + lane4];
    float4 F = Gp4[5*20 + lane4];
    float4 G = Gp4[6*20 + lane4];
    float4 Hh= Gp4[7*20 + lane4];

#define LSTM_STEP(SCUR, GV)                                                    \
    {                                                                          \
        unsigned long long aif0 = pk2(GV.x, GV.y), aif1 = 0ull;                \
        unsigned long long ago0 = pk2(GV.z, GV.w), ago1 = 0ull;                \
        const int sn_ = (SCUR) + 8;                                            \
        if (sn_ < SS) GV = Gp4[sn_ * 20 + lane4];                              \
        _Pragma("unroll")                                                      \
        for (int k = 0; k < HH; k += 2){                                       \
            float hk0 = __shfl_sync(0xffffffffu, h, k);                        \
            float hk1 = __shfl_sync(0xffffffffu, h, k + 1);                    \
            unsigned long long h20 = pk2(hk0, hk0);                            \
            unsigned long long h21 = pk2(hk1, hk1);                            \
            aif0 = ffma2v(h20, wif[k],     aif0);                              \
            aif1 = ffma2v(h21, wif[k + 1], aif1);                              \
            ago0 = ffma2v(h20, wgo[k],     ago0);                              \
            ago1 = ffma2v(h21, wgo[k + 1], ago1);                              \
        }                                                                      \
        float2 vif = upk2(add2v(aif0, aif1));                                  \
        float2 vgo = upk2(add2v(ago0, ago1));                                  \
        float si = sigm_fast(vif.x);                                           \
        float sf = sigm_fast(vif.y);                                           \
        float tg = tanha(vgo.x);                                               \
        float so = sigm_fast(vgo.y);                                           \
        c = fmaf(sf, c, si * tg);                                              \
        h = so * tanha(c);                                                     \
        if (l < HH) g_pw[((size_t)b * SS + (SCUR)) * HH + l] = h;              \
    }

    for (int s = 0; s < SS; s += 8){
        LSTM_STEP(s    , A);
        LSTM_STEP(s + 1, B);
        LSTM_STEP(s + 2, C);
        LSTM_STEP(s + 3, D);
        LSTM_STEP(s + 4, E);
        LSTM_STEP(s + 5, F);
        LSTM_STEP(s + 6, G);
        LSTM_STEP(s + 7, Hh);
    }
#undef LSTM_STEP
}

// =================================================================
// Kernel 3: mu_w / sigma projection + sequential affine scan for mu.
// (unchanged — control)
// =================================================================
__global__ __launch_bounds__(256) void k3_muscan(
    const float* __restrict__ Wmu, const float* __restrict__ bmu,
    const float* __restrict__ Wsig, const float* __restrict__ bsig)
{
    __shared__ float a_s[SS];
    __shared__ float c_s[SS];
    __shared__ float wm[3][HH];
    __shared__ float wsg[HH];
    __shared__ float bm[3];
    __shared__ float bsg;

    const int b   = blockIdx.x;
    const int tid = threadIdx.x;
    if (tid < 3*HH) wm[tid/HH][tid%HH] = Wmu[tid];
    if (tid < HH)   wsg[tid] = Wsig[tid];
    if (tid == 0){ bm[0]=bmu[0]; bm[1]=bmu[1]; bm[2]=bmu[2]; bsg = bsig[0]; }
    __syncthreads();

    for (int j = tid; j < SS; j += 256){
        const float* p = g_pw + ((size_t)b * SS + j) * HH;
        float d0 = bm[0], d1 = bm[1], d2 = bm[2], dsg = bsg;
#pragma unroll
        for (int k = 0; k < HH; ++k){
            float pv = p[k];
            d0  = fmaf(pv, wm[0][k], d0);
            d1  = fmaf(pv, wm[1][k], d1);
            d2  = fmaf(pv, wm[2][k], d2);
            dsg = fmaf(pv, wsg[k],  dsg);
        }
        float m0 = fmaxf(d0, 0.f);
        float m1 = fmaxf(d1, 0.f);
        float m2 = fmaxf(d2, 0.f);
        float sg = sigm(dsg);
        a_s[j] = m0;
        c_s[j] = m1 * (1.f/(float)SS) + m2 * ((float)(j+1) * (1.f/(float)SS));
        g_mnk[(size_t)b*SS + j] = -1.44269504088896f * __fdividef(0.5f, sg * sg);
    }
    __syncthreads();
    if (tid == 0){
        float mu = 0.f;
        float* mo = g_mu + (size_t)b * SS;
#pragma unroll 4
        for (int j = 0; j < SS; ++j){
            mu = fmaf(a_s[j], mu, c_s[j]);
            mo[j] = mu;
        }
    }
}

// =================================================================
// Kernel 4: causal gaussian attention — best-measured variant
// (unchanged — control): w plain in smem, x dup via register MOVs,
// 8j x 8d per thread, 32-t tiles, two syncthreads per tile.
// =================================================================
__global__ __launch_bounds__(256) void k4_attn(
    const float* __restrict__ x, float* __restrict__ out)
{
    __shared__ float  wsm[32][128];       // w[t][j]
    __shared__ float4 xsm[32][32];        // x[t][d/4]
    __shared__ float  ssqs[2][128];
    __shared__ float  innorm[128];

    const int jt = (int)gridDim.x - 1 - (int)blockIdx.x;  // heavy tiles first
    const int b  = blockIdx.y;
    const int j0 = jt * 128;
    const int tid = threadIdx.x;

    const int jj  = tid & 127;
    const int tch = tid >> 7;            // 0..1, 16 t's each
    const int jglob = j0 + jj;
    const float muv  = g_mu [(size_t)b*SS + jglob];
    const float mnkv = g_mnk[(size_t)b*SS + jglob];
    const float invj = __fdividef(1.f, (float)(jglob + 1));
    float ssq = 0.f;

    const int tx = tid & 15;
    const int ty = tid >> 4;
    unsigned long long acc[4][8];
#pragma unroll
    for (int p = 0; p < 4; ++p)
#pragma unroll
        for (int dd = 0; dd < 8; ++dd) acc[p][dd] = 0ull;

    const int tmax = j0 + 128;
    const float4* xg = (const float4*)(x + (size_t)b * SS * DD);

    for (int t0 = 0; t0 < tmax; t0 += 32){
        __syncthreads();
#pragma unroll
        for (int v = 0; v < 4; ++v){
            int i = v * 256 + tid;
            xsm[i >> 5][i & 31] = xg[(size_t)t0 * 32 + i];
        }
#pragma unroll
        for (int u = 0; u < 16; ++u){
            int t = t0 + tch * 16 + u;
            float tf  = (float)t;
            float dlt = fmaf(tf, invj, -muv);
            float wv  = ex2f(dlt * dlt * mnkv);
            wv = (t <= jglob) ? wv : 0.f;
            wsm[tch * 16 + u][jj] = wv;
            ssq = fmaf(wv, wv, ssq);
        }
        __syncthreads();
#pragma unroll 2
        for (int t = 0; t < 32; ++t){
            const double* wrow = (const double*)&wsm[t][0];
            unsigned long long wv0 = ((const unsigned long long*)wrow)[ty*4 + 0];
            unsigned long long wv1 = ((const unsigned long long*)wrow)[ty*4 + 1];
            unsigned long long wv2 = ((const unsigned long long*)wrow)[ty*4 + 2];
            unsigned long long wv3 = ((const unsigned long long*)wrow)[ty*4 + 3];
            float4 xa = xsm[t][tx*2];
            float4 xb = xsm[t][tx*2 + 1];
            unsigned long long xx0 = pk2(xa.x, xa.x);
            unsigned long long xx1 = pk2(xa.y, xa.y);
            unsigned long long xx2 = pk2(xa.z, xa.z);
            unsigned long long xx3 = pk2(xa.w, xa.w);
            unsigned long long xx4 = pk2(xb.x, xb.x);
            unsigned long long xx5 = pk2(xb.y, xb.y);
            unsigned long long xx6 = pk2(xb.z, xb.z);
            unsigned long long xx7 = pk2(xb.w, xb.w);
#define STEP(P, WV) \
            acc[P][0] = ffma2v(WV, xx0, acc[P][0]); \
            acc[P][1] = ffma2v(WV, xx1, acc[P][1]); \
            acc[P][2] = ffma2v(WV, xx2, acc[P][2]); \
            acc[P][3] = ffma2v(WV, xx3, acc[P][3]); \
            acc[P][4] = ffma2v(WV, xx4, acc[P][4]); \
            acc[P][5] = ffma2v(WV, xx5, acc[P][5]); \
            acc[P][6] = ffma2v(WV, xx6, acc[P][6]); \
            acc[P][7] = ffma2v(WV, xx7, acc[P][7]);
            STEP(0, wv0) STEP(1, wv1) STEP(2, wv2) STEP(3, wv3)
#undef STEP
        }
    }

    __syncthreads();
    ssqs[tch][jj] = ssq;
    __syncthreads();
    if (tid < 128){
        float s2 = ssqs[0][tid] + ssqs[1][tid];
        innorm[tid] = __fdividef(1.f, fmaxf(sqrtf(s2), 1e-12f));
    }
    __syncthreads();

    const int d0 = tx * 8;
#pragma unroll
    for (int p = 0; p < 4; ++p){
        int jl = ty * 8 + p * 2;
        int j  = j0 + jl;
        float i0 = innorm[jl];
        float i1 = innorm[jl + 1];
        float2 q0 = upk2(acc[p][0]);
        float2 q1 = upk2(acc[p][1]);
        float2 q2 = upk2(acc[p][2]);
        float2 q3 = upk2(acc[p][3]);
        float2 q4 = upk2(acc[p][4]);
        float2 q5 = upk2(acc[p][5]);
        float2 q6 = upk2(acc[p][6]);
        float2 q7 = upk2(acc[p][7]);
        float4* o0 = (float4*)&out[((size_t)b * SS + j    ) * DD + d0];
        float4* o1 = (float4*)&out[((size_t)b * SS + j + 1) * DD + d0];
        o0[0] = make_float4(q0.x*i0, q1.x*i0, q2.x*i0, q3.x*i0);
        o0[1] = make_float4(q4.x*i0, q5.x*i0, q6.x*i0, q7.x*i0);
        o1[0] = make_float4(q0.y*i1, q1.y*i1, q2.y*i1, q3.y*i1);
        o1[1] = make_float4(q4.y*i1, q5.y*i1, q6.y*i1, q7.y*i1);
    }
}

// =================================================================
extern "C" void kernel_launch(void* const* d_in, const int* in_sizes, int n_in,
                              void* d_out, int out_size)
{
    const float* x    = (const float*)d_in[0];
    const float* Wih  = (const float*)d_in[1];
    const float* Whh  = (const float*)d_in[2];
    const float* bih  = (const float*)d_in[3];
    const float* bhh  = (const float*)d_in[4];
    const float* Wmu  = (const float*)d_in[5];
    const float* bmu  = (const float*)d_in[6];
    const float* Wsig = (const float*)d_in[7];
    const float* bsig = (const float*)d_in[8];
    float* out = (float*)d_out;

    k1_gates<<<(BB*SS)/64, 256>>>(x, Wih, bih, bhh);
    k2_lstm <<<BB, 32>>>(Whh);
    k3_muscan<<<BB, 256>>>(Wmu, bmu, Wsig, bsig);
    dim3 g4(SS/128, BB);
    k4_attn<<<g4, 256>>>(x, out);
}